// round 6
// baseline (speedup 1.0000x reference)
#include <cuda_runtime.h>
#include <cstdint>

#define FULL 0xFFFFFFFFu

constexpr int N_RAYS    = 8192;
constexpr int N_SAMPLES = 512;
constexpr int HID       = 32;
constexpr int WARPS_PER_BLOCK = 8;
constexpr int TPT       = 16;   // samples per thread

using ull = unsigned long long;

// ---- packed f32x2 helpers (sm_103a) ----
__device__ __forceinline__ ull pk2(float lo, float hi) {
    ull r; asm("mov.b64 %0, {%1, %2};" : "=l"(r) : "f"(lo), "f"(hi)); return r;
}
__device__ __forceinline__ void upk2(ull v, float& lo, float& hi) {
    asm("mov.b64 {%0, %1}, %2;" : "=f"(lo), "=f"(hi) : "l"(v));
}
__device__ __forceinline__ ull fma2_(ull a, ull b, ull c) {
    ull r; asm("fma.rn.f32x2 %0, %1, %2, %3;" : "=l"(r) : "l"(a), "l"(b), "l"(c)); return r;
}
__device__ __forceinline__ ull add2_(ull a, ull b) {
    ull r; asm("add.rn.f32x2 %0, %1, %2;" : "=l"(r) : "l"(a), "l"(b)); return r;
}
// 2*relu(x) per half: x + |x|   (layer-2 weights pre-scaled by 0.5)
__device__ __forceinline__ ull relu2x(ull h) {
    union { ull u; uint2 v; } a, m;
    a.u = h;
    m.v.x = a.v.x & 0x7fffffffu;
    m.v.y = a.v.y & 0x7fffffffu;
    return add2_(h, m.u);
}

__device__ __forceinline__ float sigmoidf_fast(float x) {
    return __fdividef(1.0f, 1.0f + __expf(-x));
}
__device__ __forceinline__ float softplusf_fast(float x) {
    return fmaxf(x, 0.0f) + __logf(1.0f + __expf(-fabsf(x)));
}

__global__ __launch_bounds__(WARPS_PER_BLOCK * 32, 3)
void nerf_render_kernel(
    const float* __restrict__ o,    // [N,3]
    const float* __restrict__ dI,   // [N,3]
    const float* __restrict__ aabb, // [2,3]
    const float* __restrict__ u,    // [N,512]
    const float* __restrict__ W1,   // [3,32]
    const float* __restrict__ b1,   // [32]
    const float* __restrict__ Wc,   // [32,3]
    const float* __restrict__ bc,   // [3]
    const float* __restrict__ Wd,   // [32,1]
    const float* __restrict__ bd,   // [1]
    float* __restrict__ out)        // [N,4]
{
    // weight tables: each entry = two duplicated (w,w) f32x2 packs -> one LDS.128
    __shared__ ulonglong2 sAB[HID], sCD[HID], sEF[HID], sGH[HID];
    __shared__ float sbias[4];

    const int tx = threadIdx.x;
    if (tx < HID) {
        const float wx = W1[tx], wy = W1[HID + tx], wz = W1[2 * HID + tx], wb = b1[tx];
        sAB[tx] = make_ulonglong2(pk2(wx, wx), pk2(wy, wy));
        sCD[tx] = make_ulonglong2(pk2(wz, wz), pk2(wb, wb));
        const float cx = 0.5f * Wc[3 * tx], cy = 0.5f * Wc[3 * tx + 1];
        const float cz = 0.5f * Wc[3 * tx + 2], cw = 0.5f * Wd[tx];
        sEF[tx] = make_ulonglong2(pk2(cx, cx), pk2(cy, cy));
        sGH[tx] = make_ulonglong2(pk2(cz, cz), pk2(cw, cw));
    }
    if (tx == HID) { sbias[0] = bc[0]; sbias[1] = bc[1]; sbias[2] = bc[2]; sbias[3] = bd[0]; }
    __syncthreads();

    const int warp = tx >> 5;
    const int lane = tx & 31;
    const int r = blockIdx.x * WARPS_PER_BLOCK + warp;

    const float ox = o[3 * r], oy = o[3 * r + 1], oz = o[3 * r + 2];
    const float dx = dI[3 * r], dy = dI[3 * r + 1], dz = dI[3 * r + 2];
    const float mn0 = aabb[0], mn1 = aabb[1], mn2 = aabb[2];
    const float mx0 = aabb[3], mx1 = aabb[4], mx2 = aabb[5];

    float t1, t2;
    t1 = (mn0 - ox) / dx; t2 = (mx0 - ox) / dx;
    float tn = fminf(t1, t2), tf = fmaxf(t1, t2);
    t1 = (mn1 - oy) / dy; t2 = (mx1 - oy) / dy;
    tn = fmaxf(tn, fminf(t1, t2)); tf = fminf(tf, fmaxf(t1, t2));
    t1 = (mn2 - oz) / dz; t2 = (mx2 - oz) / dz;
    tn = fmaxf(tn, fminf(t1, t2)); tf = fminf(tf, fmaxf(t1, t2));
    tn = fmaxf(tn, 0.0f);

    if (!(tn < tf)) {
        if (lane == 0) reinterpret_cast<float4*>(out)[r] = make_float4(0.f, 0.f, 0.f, 0.f);
        return;
    }

    const float dnorm  = sqrtf(dx * dx + dy * dy + dz * dz);
    const float scaleT = (tf - tn) * (1.0f / (float)N_SAMPLES);
    const float dscale = scaleT * dnorm;
    const float g0 = 2.0f / (mx0 - mn0);
    const float g1 = 2.0f / (mx1 - mn1);
    const float g2 = 2.0f / (mx2 - mn2);
    const float bcr = sbias[0], bcg = sbias[1], bcb = sbias[2], bdd = sbias[3];

    const float4* u4 = reinterpret_cast<const float4*>(u + (size_t)r * N_SAMPLES) + lane * 4;
    float4 uv = u4[0];
    const float nb = __shfl_down_sync(FULL, uv.x, 1);   // lane 31's value unused (t==511 path)

    const int base = lane * TPT;

    float e_run = 1.0f, Psum = 0.0f;
    float ar = 0.f, ag = 0.f, ab = 0.f, aw = 0.f;

    #pragma unroll 1
    for (int i = 0; i < 4; ++i) {
        const float u0 = uv.x, u1 = uv.y, u2v = uv.z, u3 = uv.w;
        float un;
        if (i < 3) { uv = u4[i + 1]; un = uv.x; }
        else       { un = nb; }
        const int t0 = base + 4 * i;

        // ---- geometry for 4 samples
        float n00, n01, n02, n10, n11, n12, n20, n21, n22, n30, n31, n32, ts3;
        {
            const float ts = fmaf(scaleT, (float)(t0 + 0) + u0, tn);
            const float x = fmaf(dx, ts, ox), y = fmaf(dy, ts, oy), z = fmaf(dz, ts, oz);
            n00 = fmaf(x - mn0, g0, -1.0f); n01 = fmaf(y - mn1, g1, -1.0f); n02 = fmaf(z - mn2, g2, -1.0f);
        }
        {
            const float ts = fmaf(scaleT, (float)(t0 + 1) + u1, tn);
            const float x = fmaf(dx, ts, ox), y = fmaf(dy, ts, oy), z = fmaf(dz, ts, oz);
            n10 = fmaf(x - mn0, g0, -1.0f); n11 = fmaf(y - mn1, g1, -1.0f); n12 = fmaf(z - mn2, g2, -1.0f);
        }
        {
            const float ts = fmaf(scaleT, (float)(t0 + 2) + u2v, tn);
            const float x = fmaf(dx, ts, ox), y = fmaf(dy, ts, oy), z = fmaf(dz, ts, oz);
            n20 = fmaf(x - mn0, g0, -1.0f); n21 = fmaf(y - mn1, g1, -1.0f); n22 = fmaf(z - mn2, g2, -1.0f);
        }
        {
            ts3 = fmaf(scaleT, (float)(t0 + 3) + u3, tn);
            const float x = fmaf(dx, ts3, ox), y = fmaf(dy, ts3, oy), z = fmaf(dz, ts3, oz);
            n30 = fmaf(x - mn0, g0, -1.0f); n31 = fmaf(y - mn1, g1, -1.0f); n32 = fmaf(z - mn2, g2, -1.0f);
        }
        const bool ib0 = (fabsf(n00) <= 1.f) & (fabsf(n01) <= 1.f) & (fabsf(n02) <= 1.f);
        const bool ib1 = (fabsf(n10) <= 1.f) & (fabsf(n11) <= 1.f) & (fabsf(n12) <= 1.f);
        const bool ib2 = (fabsf(n20) <= 1.f) & (fabsf(n21) <= 1.f) & (fabsf(n22) <= 1.f);
        const bool ib3 = (fabsf(n30) <= 1.f) & (fabsf(n31) <= 1.f) & (fabsf(n32) <= 1.f);
        const float dl0 = dscale * (1.0f + u1 - u0);
        const float dl1 = dscale * (1.0f + u2v - u1);
        const float dl2 = dscale * (1.0f + u3 - u2v);
        float dl3 = dscale * (1.0f + un - u3);
        if (t0 + 3 == N_SAMPLES - 1) dl3 = (tf + 1.0f - ts3) * dnorm;

        // ---- packed MLP: pack a = (s0,s1), pack b = (s2,s3); weights loaded once per j
        const ull pn0a = pk2(n00, n10), pn1a = pk2(n01, n11), pn2a = pk2(n02, n12);
        const ull pn0b = pk2(n20, n30), pn1b = pk2(n21, n31), pn2b = pk2(n22, n32);

        ull pra = 0, pga = 0, pba = 0, pda = 0;
        ull prb = 0, pgb = 0, pbb = 0, pdb = 0;
        #pragma unroll 2
        for (int j = 0; j < HID; ++j) {
            const ulonglong2 wab = sAB[j];
            const ulonglong2 wcd = sCD[j];
            ull ha = fma2_(pn0a, wab.x, fma2_(pn1a, wab.y, fma2_(pn2a, wcd.x, wcd.y)));
            ull hb = fma2_(pn0b, wab.x, fma2_(pn1b, wab.y, fma2_(pn2b, wcd.x, wcd.y)));
            ha = relu2x(ha);
            hb = relu2x(hb);
            const ulonglong2 wef = sEF[j];
            const ulonglong2 wgh = sGH[j];
            pra = fma2_(ha, wef.x, pra); pga = fma2_(ha, wef.y, pga);
            pba = fma2_(ha, wgh.x, pba); pda = fma2_(ha, wgh.y, pda);
            prb = fma2_(hb, wef.x, prb); pgb = fma2_(hb, wef.y, pgb);
            pbb = fma2_(hb, wgh.x, pbb); pdb = fma2_(hb, wgh.y, pdb);
        }

        float c0r, c1r, c0g, c1g, c0b, c1b, d0, d1;
        float c2r, c3r, c2g, c3g, c2b, c3b, d2, d3;
        upk2(pra, c0r, c1r); upk2(pga, c0g, c1g); upk2(pba, c0b, c1b); upk2(pda, d0, d1);
        upk2(prb, c2r, c3r); upk2(pgb, c2g, c3g); upk2(pbb, c2b, c3b); upk2(pdb, d2, d3);

        // ---- sequential compositing (order matters)
        {
            const float cr = sigmoidf_fast(c0r + bcr), cg = sigmoidf_fast(c0g + bcg), cb = sigmoidf_fast(c0b + bcb);
            float den = softplusf_fast(d0 + bdd); if (!ib0) den = 0.0f;
            const float sd = den * dl0, esd = __expf(-sd);
            const float wl = e_run - e_run * esd;
            ar = fmaf(wl, cr, ar); ag = fmaf(wl, cg, ag); ab = fmaf(wl, cb, ab); aw += wl;
            e_run *= esd; Psum += sd;
        }
        {
            const float cr = sigmoidf_fast(c1r + bcr), cg = sigmoidf_fast(c1g + bcg), cb = sigmoidf_fast(c1b + bcb);
            float den = softplusf_fast(d1 + bdd); if (!ib1) den = 0.0f;
            const float sd = den * dl1, esd = __expf(-sd);
            const float wl = e_run - e_run * esd;
            ar = fmaf(wl, cr, ar); ag = fmaf(wl, cg, ag); ab = fmaf(wl, cb, ab); aw += wl;
            e_run *= esd; Psum += sd;
        }
        {
            const float cr = sigmoidf_fast(c2r + bcr), cg = sigmoidf_fast(c2g + bcg), cb = sigmoidf_fast(c2b + bcb);
            float den = softplusf_fast(d2 + bdd); if (!ib2) den = 0.0f;
            const float sd = den * dl2, esd = __expf(-sd);
            const float wl = e_run - e_run * esd;
            ar = fmaf(wl, cr, ar); ag = fmaf(wl, cg, ag); ab = fmaf(wl, cb, ab); aw += wl;
            e_run *= esd; Psum += sd;
        }
        {
            const float cr = sigmoidf_fast(c3r + bcr), cg = sigmoidf_fast(c3g + bcg), cb = sigmoidf_fast(c3b + bcb);
            float den = softplusf_fast(d3 + bdd); if (!ib3) den = 0.0f;
            const float sd = den * dl3, esd = __expf(-sd);
            const float wl = e_run - e_run * esd;
            ar = fmaf(wl, cr, ar); ag = fmaf(wl, cg, ag); ab = fmaf(wl, cb, ab); aw += wl;
            e_run *= esd; Psum += sd;
        }
    }

    // ---- warp exclusive scan of optical depth -> per-lane transmittance base
    float inc = Psum;
    #pragma unroll
    for (int off = 1; off < 32; off <<= 1) {
        float y = __shfl_up_sync(FULL, inc, off);
        if (lane >= off) inc += y;
    }
    float excl = __shfl_up_sync(FULL, inc, 1);
    if (lane == 0) excl = 0.0f;
    const float sc = __expf(-excl);
    ar *= sc; ag *= sc; ab *= sc; aw *= sc;

    #pragma unroll
    for (int off = 16; off > 0; off >>= 1) {
        ar += __shfl_xor_sync(FULL, ar, off);
        ag += __shfl_xor_sync(FULL, ag, off);
        ab += __shfl_xor_sync(FULL, ab, off);
        aw += __shfl_xor_sync(FULL, aw, off);
    }

    if (lane == 0)
        reinterpret_cast<float4*>(out)[r] = make_float4(ar, ag, ab, aw);
}

extern "C" void kernel_launch(void* const* d_in, const int* in_sizes, int n_in,
                              void* d_out, int out_size) {
    const float* o    = (const float*)d_in[0];
    const float* dI   = (const float*)d_in[1];
    const float* aabb = (const float*)d_in[2];
    const float* u    = (const float*)d_in[3];
    const float* W1   = (const float*)d_in[4];
    const float* b1   = (const float*)d_in[5];
    const float* Wc   = (const float*)d_in[6];
    const float* bc   = (const float*)d_in[7];
    const float* Wd   = (const float*)d_in[8];
    const float* bd   = (const float*)d_in[9];
    float* out = (float*)d_out;

    dim3 grid(N_RAYS / WARPS_PER_BLOCK);
    dim3 block(WARPS_PER_BLOCK * 32);
    nerf_render_kernel<<<grid, block>>>(o, dI, aabb, u, W1, b1, Wc, bc, Wd, bd, out);
}

// round 7
// speedup vs baseline: 1.1267x; 1.1267x over previous
#include <cuda_runtime.h>
#include <cstdint>

#define FULL 0xFFFFFFFFu

constexpr int N_RAYS    = 8192;
constexpr int N_SAMPLES = 512;
constexpr int HID       = 32;
constexpr int WARPS_PER_BLOCK = 8;
constexpr int TPT       = 16;   // samples per thread

using ull = unsigned long long;

// ---- packed f32x2 helpers (sm_103a) ----
__device__ __forceinline__ ull pk2(float lo, float hi) {
    ull r; asm("mov.b64 %0, {%1, %2};" : "=l"(r) : "f"(lo), "f"(hi)); return r;
}
__device__ __forceinline__ void upk2(ull v, float& lo, float& hi) {
    asm("mov.b64 {%0, %1}, %2;" : "=f"(lo), "=f"(hi) : "l"(v));
}
__device__ __forceinline__ ull fma2_(ull a, ull b, ull c) {
    ull r; asm("fma.rn.f32x2 %0, %1, %2, %3;" : "=l"(r) : "l"(a), "l"(b), "l"(c)); return r;
}
// relu per half via FMNMX (alu pipe); pair aliasing -> no real movs
__device__ __forceinline__ ull relu2(ull h) {
    float lo, hi; upk2(h, lo, hi);
    lo = fmaxf(lo, 0.0f); hi = fmaxf(hi, 0.0f);
    return pk2(lo, hi);
}

__device__ __forceinline__ float sigmoidf_fast(float x) {
    return __fdividef(1.0f, 1.0f + __expf(-x));
}
__device__ __forceinline__ float softplusf_fast(float x) {
    return fmaxf(x, 0.0f) + __logf(1.0f + __expf(-fabsf(x)));
}

__global__ __launch_bounds__(WARPS_PER_BLOCK * 32, 2)
void nerf_render_kernel(
    const float* __restrict__ o,    // [N,3]
    const float* __restrict__ dI,   // [N,3]
    const float* __restrict__ aabb, // [2,3]
    const float* __restrict__ u,    // [N,512]
    const float* __restrict__ W1,   // [3,32]
    const float* __restrict__ b1,   // [32]
    const float* __restrict__ Wc,   // [32,3]
    const float* __restrict__ bc,   // [3]
    const float* __restrict__ Wd,   // [32,1]
    const float* __restrict__ bd,   // [1]
    float* __restrict__ out)        // [N,4]
{
    // weight tables: each entry = two duplicated (w,w) f32x2 packs -> one LDS.128
    __shared__ ulonglong2 sAB[HID], sCD[HID], sEF[HID], sGH[HID];
    __shared__ float sbias[4];

    const int tx = threadIdx.x;
    if (tx < HID) {
        const float wx = W1[tx], wy = W1[HID + tx], wz = W1[2 * HID + tx], wb = b1[tx];
        sAB[tx] = make_ulonglong2(pk2(wx, wx), pk2(wy, wy));
        sCD[tx] = make_ulonglong2(pk2(wz, wz), pk2(wb, wb));
        const float cx = Wc[3 * tx], cy = Wc[3 * tx + 1];
        const float cz = Wc[3 * tx + 2], cw = Wd[tx];
        sEF[tx] = make_ulonglong2(pk2(cx, cx), pk2(cy, cy));
        sGH[tx] = make_ulonglong2(pk2(cz, cz), pk2(cw, cw));
    }
    if (tx == HID) { sbias[0] = bc[0]; sbias[1] = bc[1]; sbias[2] = bc[2]; sbias[3] = bd[0]; }
    __syncthreads();

    const int warp = tx >> 5;
    const int lane = tx & 31;
    const int r = blockIdx.x * WARPS_PER_BLOCK + warp;

    const float ox = o[3 * r], oy = o[3 * r + 1], oz = o[3 * r + 2];
    const float dx = dI[3 * r], dy = dI[3 * r + 1], dz = dI[3 * r + 2];
    const float mn0 = aabb[0], mn1 = aabb[1], mn2 = aabb[2];
    const float mx0 = aabb[3], mx1 = aabb[4], mx2 = aabb[5];

    float t1, t2;
    t1 = (mn0 - ox) / dx; t2 = (mx0 - ox) / dx;
    float tn = fminf(t1, t2), tf = fmaxf(t1, t2);
    t1 = (mn1 - oy) / dy; t2 = (mx1 - oy) / dy;
    tn = fmaxf(tn, fminf(t1, t2)); tf = fminf(tf, fmaxf(t1, t2));
    t1 = (mn2 - oz) / dz; t2 = (mx2 - oz) / dz;
    tn = fmaxf(tn, fminf(t1, t2)); tf = fminf(tf, fmaxf(t1, t2));
    tn = fmaxf(tn, 0.0f);

    if (!(tn < tf)) {
        if (lane == 0) reinterpret_cast<float4*>(out)[r] = make_float4(0.f, 0.f, 0.f, 0.f);
        return;
    }

    const float dnorm  = sqrtf(dx * dx + dy * dy + dz * dz);
    const float scaleT = (tf - tn) * (1.0f / (float)N_SAMPLES);
    const float dscale = scaleT * dnorm;
    const float g0 = 2.0f / (mx0 - mn0);
    const float g1 = 2.0f / (mx1 - mn1);
    const float g2 = 2.0f / (mx2 - mn2);
    const float bcr = sbias[0], bcg = sbias[1], bcb = sbias[2], bdd = sbias[3];

    const float4* u4 = reinterpret_cast<const float4*>(u + (size_t)r * N_SAMPLES) + lane * 4;
    float4 ua = u4[0], ub = u4[1];
    const float nbv = __shfl_down_sync(FULL, ua.x, 1);   // lane 31's value unused (t==511 path)

    const int base = lane * TPT;

    float e_run = 1.0f, Psum = 0.0f;
    float ar = 0.f, ag = 0.f, ab = 0.f, aw = 0.f;

    #pragma unroll 1
    for (int i = 0; i < 2; ++i) {
        // u values for samples s0..s7 of this half
        const float us0 = ua.x, us1 = ua.y, us2 = ua.z, us3 = ua.w;
        const float us4 = ub.x, us5 = ub.y, us6 = ub.z, us7 = ub.w;
        float4 na, nb4;
        float un;
        if (i == 0) { na = u4[2]; nb4 = u4[3]; un = na.x; }
        else        { un = nbv; }
        const int t0 = base + 8 * i;

        // ---- geometry for 8 samples -> 12 packed n-values
        float nx[8], ny[8], nz[8], uu[9];
        uu[0]=us0; uu[1]=us1; uu[2]=us2; uu[3]=us3; uu[4]=us4; uu[5]=us5; uu[6]=us6; uu[7]=us7; uu[8]=un;
        float ts7;
        #pragma unroll
        for (int s = 0; s < 8; ++s) {
            const float ts = fmaf(scaleT, (float)(t0 + s) + uu[s], tn);
            if (s == 7) ts7 = ts;
            const float x = fmaf(dx, ts, ox), y = fmaf(dy, ts, oy), z = fmaf(dz, ts, oz);
            nx[s] = fmaf(x - mn0, g0, -1.0f);
            ny[s] = fmaf(y - mn1, g1, -1.0f);
            nz[s] = fmaf(z - mn2, g2, -1.0f);
        }
        bool ib[8];
        float dl[8];
        #pragma unroll
        for (int s = 0; s < 8; ++s) {
            ib[s] = (fabsf(nx[s]) <= 1.f) & (fabsf(ny[s]) <= 1.f) & (fabsf(nz[s]) <= 1.f);
            dl[s] = dscale * (1.0f + uu[s + 1] - uu[s]);
        }
        if (t0 + 7 == N_SAMPLES - 1) dl[7] = (tf + 1.0f - ts7) * dnorm;

        // packs: A=(s0,s1) B=(s2,s3) C=(s4,s5) D=(s6,s7)
        const ull p0A = pk2(nx[0], nx[1]), p1A = pk2(ny[0], ny[1]), p2A = pk2(nz[0], nz[1]);
        const ull p0B = pk2(nx[2], nx[3]), p1B = pk2(ny[2], ny[3]), p2B = pk2(nz[2], nz[3]);
        const ull p0C = pk2(nx[4], nx[5]), p1C = pk2(ny[4], ny[5]), p2C = pk2(nz[4], nz[5]);
        const ull p0D = pk2(nx[6], nx[7]), p1D = pk2(ny[6], ny[7]), p2D = pk2(nz[6], nz[7]);

        ull prA = 0, pgA = 0, pbA = 0, pdA = 0;
        ull prB = 0, pgB = 0, pbB = 0, pdB = 0;
        ull prC = 0, pgC = 0, pbC = 0, pdC = 0;
        ull prD = 0, pgD = 0, pbD = 0, pdD = 0;

        #pragma unroll 2
        for (int j = 0; j < HID; ++j) {
            const ulonglong2 wab = sAB[j];
            const ulonglong2 wcd = sCD[j];
            ull hA = fma2_(p0A, wab.x, fma2_(p1A, wab.y, fma2_(p2A, wcd.x, wcd.y)));
            ull hB = fma2_(p0B, wab.x, fma2_(p1B, wab.y, fma2_(p2B, wcd.x, wcd.y)));
            ull hC = fma2_(p0C, wab.x, fma2_(p1C, wab.y, fma2_(p2C, wcd.x, wcd.y)));
            ull hD = fma2_(p0D, wab.x, fma2_(p1D, wab.y, fma2_(p2D, wcd.x, wcd.y)));
            hA = relu2(hA); hB = relu2(hB); hC = relu2(hC); hD = relu2(hD);
            const ulonglong2 wef = sEF[j];
            const ulonglong2 wgh = sGH[j];
            prA = fma2_(hA, wef.x, prA); pgA = fma2_(hA, wef.y, pgA);
            pbA = fma2_(hA, wgh.x, pbA); pdA = fma2_(hA, wgh.y, pdA);
            prB = fma2_(hB, wef.x, prB); pgB = fma2_(hB, wef.y, pgB);
            pbB = fma2_(hB, wgh.x, pbB); pdB = fma2_(hB, wgh.y, pdB);
            prC = fma2_(hC, wef.x, prC); pgC = fma2_(hC, wef.y, pgC);
            pbC = fma2_(hC, wgh.x, pbC); pdC = fma2_(hC, wgh.y, pdC);
            prD = fma2_(hD, wef.x, prD); pgD = fma2_(hD, wef.y, pgD);
            pbD = fma2_(hD, wgh.x, pbD); pdD = fma2_(hD, wgh.y, pdD);
        }

        // ---- unpack + sequential compositing (order matters)
        float cr0, cr1, cg0, cg1, cb0, cb1, dd0, dd1;
        #pragma unroll
        for (int q = 0; q < 4; ++q) {
            ull pr, pg, pb, pd;
            if (q == 0)      { pr = prA; pg = pgA; pb = pbA; pd = pdA; }
            else if (q == 1) { pr = prB; pg = pgB; pb = pbB; pd = pdB; }
            else if (q == 2) { pr = prC; pg = pgC; pb = pbC; pd = pdC; }
            else             { pr = prD; pg = pgD; pb = pbD; pd = pdD; }
            upk2(pr, cr0, cr1); upk2(pg, cg0, cg1); upk2(pb, cb0, cb1); upk2(pd, dd0, dd1);
            const int s0 = 2 * q, s1 = 2 * q + 1;
            {
                const float cr = sigmoidf_fast(cr0 + bcr), cg = sigmoidf_fast(cg0 + bcg), cb = sigmoidf_fast(cb0 + bcb);
                float den = softplusf_fast(dd0 + bdd); if (!ib[s0]) den = 0.0f;
                const float sd = den * dl[s0], esd = __expf(-sd);
                const float wl = e_run - e_run * esd;
                ar = fmaf(wl, cr, ar); ag = fmaf(wl, cg, ag); ab = fmaf(wl, cb, ab); aw += wl;
                e_run *= esd; Psum += sd;
            }
            {
                const float cr = sigmoidf_fast(cr1 + bcr), cg = sigmoidf_fast(cg1 + bcg), cb = sigmoidf_fast(cb1 + bcb);
                float den = softplusf_fast(dd1 + bdd); if (!ib[s1]) den = 0.0f;
                const float sd = den * dl[s1], esd = __expf(-sd);
                const float wl = e_run - e_run * esd;
                ar = fmaf(wl, cr, ar); ag = fmaf(wl, cg, ag); ab = fmaf(wl, cb, ab); aw += wl;
                e_run *= esd; Psum += sd;
            }
        }

        ua = na; ub = nb4;
    }

    // ---- warp exclusive scan of optical depth -> per-lane transmittance base
    float inc = Psum;
    #pragma unroll
    for (int off = 1; off < 32; off <<= 1) {
        float y = __shfl_up_sync(FULL, inc, off);
        if (lane >= off) inc += y;
    }
    float excl = __shfl_up_sync(FULL, inc, 1);
    if (lane == 0) excl = 0.0f;
    const float sc = __expf(-excl);
    ar *= sc; ag *= sc; ab *= sc; aw *= sc;

    #pragma unroll
    for (int off = 16; off > 0; off >>= 1) {
        ar += __shfl_xor_sync(FULL, ar, off);
        ag += __shfl_xor_sync(FULL, ag, off);
        ab += __shfl_xor_sync(FULL, ab, off);
        aw += __shfl_xor_sync(FULL, aw, off);
    }

    if (lane == 0)
        reinterpret_cast<float4*>(out)[r] = make_float4(ar, ag, ab, aw);
}

extern "C" void kernel_launch(void* const* d_in, const int* in_sizes, int n_in,
                              void* d_out, int out_size) {
    const float* o    = (const float*)d_in[0];
    const float* dI   = (const float*)d_in[1];
    const float* aabb = (const float*)d_in[2];
    const float* u    = (const float*)d_in[3];
    const float* W1   = (const float*)d_in[4];
    const float* b1   = (const float*)d_in[5];
    const float* Wc   = (const float*)d_in[6];
    const float* bc   = (const float*)d_in[7];
    const float* Wd   = (const float*)d_in[8];
    const float* bd   = (const float*)d_in[9];
    float* out = (float*)d_out;

    dim3 grid(N_RAYS / WARPS_PER_BLOCK);
    dim3 block(WARPS_PER_BLOCK * 32);
    nerf_render_kernel<<<grid, block>>>(o, dI, aabb, u, W1, b1, Wc, bc, Wd, bd, out);
}

// round 8
// speedup vs baseline: 1.1460x; 1.0171x over previous
#include <cuda_runtime.h>
#include <cstdint>

#define FULL 0xFFFFFFFFu

constexpr int N_RAYS    = 8192;
constexpr int N_SAMPLES = 512;
constexpr int HID       = 32;
constexpr int WARPS_PER_BLOCK = 8;
constexpr int TPT       = 16;   // samples per thread

using ull = unsigned long long;

// ---- packed f32x2 helpers (sm_103a) ----
__device__ __forceinline__ ull pk2(float lo, float hi) {
    ull r; asm("mov.b64 %0, {%1, %2};" : "=l"(r) : "f"(lo), "f"(hi)); return r;
}
__device__ __forceinline__ void upk2(ull v, float& lo, float& hi) {
    asm("mov.b64 {%0, %1}, %2;" : "=f"(lo), "=f"(hi) : "l"(v));
}
__device__ __forceinline__ ull fma2_(ull a, ull b, ull c) {
    ull r; asm("fma.rn.f32x2 %0, %1, %2, %3;" : "=l"(r) : "l"(a), "l"(b), "l"(c)); return r;
}
// relu per half via FMNMX (alu pipe); pair aliasing -> no real movs
__device__ __forceinline__ ull relu2(ull h) {
    float lo, hi; upk2(h, lo, hi);
    lo = fmaxf(lo, 0.0f); hi = fmaxf(hi, 0.0f);
    return pk2(lo, hi);
}

__device__ __forceinline__ float sigmoidf_fast(float x) {
    return __fdividef(1.0f, 1.0f + __expf(-x));
}
__device__ __forceinline__ float softplusf_fast(float x) {
    return fmaxf(x, 0.0f) + __logf(1.0f + __expf(-fabsf(x)));
}

__global__ __launch_bounds__(WARPS_PER_BLOCK * 32, 2)
void nerf_render_kernel(
    const float* __restrict__ o,    // [N,3]
    const float* __restrict__ dI,   // [N,3]
    const float* __restrict__ aabb, // [2,3]
    const float* __restrict__ u,    // [N,512]
    const float* __restrict__ W1,   // [3,32]
    const float* __restrict__ b1,   // [32]
    const float* __restrict__ Wc,   // [32,3]
    const float* __restrict__ bc,   // [3]
    const float* __restrict__ Wd,   // [32,1]
    const float* __restrict__ bd,   // [1]
    float* __restrict__ out)        // [N,4]
{
    // weight tables: each entry = two duplicated (w,w) f32x2 packs -> one LDS.128
    __shared__ ulonglong2 sAB[HID], sCD[HID], sEF[HID], sGH[HID];
    __shared__ float sbias[4];

    const int tx = threadIdx.x;
    if (tx < HID) {
        const float wx = W1[tx], wy = W1[HID + tx], wz = W1[2 * HID + tx], wb = b1[tx];
        sAB[tx] = make_ulonglong2(pk2(wx, wx), pk2(wy, wy));
        sCD[tx] = make_ulonglong2(pk2(wz, wz), pk2(wb, wb));
        const float cx = Wc[3 * tx], cy = Wc[3 * tx + 1];
        const float cz = Wc[3 * tx + 2], cw = Wd[tx];
        sEF[tx] = make_ulonglong2(pk2(cx, cx), pk2(cy, cy));
        sGH[tx] = make_ulonglong2(pk2(cz, cz), pk2(cw, cw));
    }
    if (tx == HID) { sbias[0] = bc[0]; sbias[1] = bc[1]; sbias[2] = bc[2]; sbias[3] = bd[0]; }
    __syncthreads();

    const int warp = tx >> 5;
    const int lane = tx & 31;
    const int r = blockIdx.x * WARPS_PER_BLOCK + warp;

    const float ox = o[3 * r], oy = o[3 * r + 1], oz = o[3 * r + 2];
    const float dx = dI[3 * r], dy = dI[3 * r + 1], dz = dI[3 * r + 2];
    const float mn0 = aabb[0], mn1 = aabb[1], mn2 = aabb[2];
    const float mx0 = aabb[3], mx1 = aabb[4], mx2 = aabb[5];

    float t1, t2;
    t1 = (mn0 - ox) / dx; t2 = (mx0 - ox) / dx;
    float tn = fminf(t1, t2), tf = fmaxf(t1, t2);
    t1 = (mn1 - oy) / dy; t2 = (mx1 - oy) / dy;
    tn = fmaxf(tn, fminf(t1, t2)); tf = fminf(tf, fmaxf(t1, t2));
    t1 = (mn2 - oz) / dz; t2 = (mx2 - oz) / dz;
    tn = fmaxf(tn, fminf(t1, t2)); tf = fminf(tf, fmaxf(t1, t2));
    tn = fmaxf(tn, 0.0f);

    if (!(tn < tf)) {
        if (lane == 0) reinterpret_cast<float4*>(out)[r] = make_float4(0.f, 0.f, 0.f, 0.f);
        return;
    }

    const float dnorm  = sqrtf(dx * dx + dy * dy + dz * dz);
    const float scaleT = (tf - tn) * (1.0f / (float)N_SAMPLES);
    const float dscale = scaleT * dnorm;
    const float g0 = 2.0f / (mx0 - mn0);
    const float g1 = 2.0f / (mx1 - mn1);
    const float g2 = 2.0f / (mx2 - mn2);
    const float bcr = sbias[0], bcg = sbias[1], bcb = sbias[2], bdd = sbias[3];

    const float4* u4 = reinterpret_cast<const float4*>(u + (size_t)r * N_SAMPLES) + lane * 4;
    float4 ua = u4[0], ub = u4[1];
    const float nbv = __shfl_down_sync(FULL, ua.x, 1);   // lane 31's value unused (t==511 path)

    const int base = lane * TPT;

    float e_run = 1.0f, Psum = 0.0f;
    float ar = 0.f, ag = 0.f, ab = 0.f, aw = 0.f;

    #pragma unroll 1
    for (int i = 0; i < 2; ++i) {
        // u values for samples s0..s7 of this half
        const float us0 = ua.x, us1 = ua.y, us2 = ua.z, us3 = ua.w;
        const float us4 = ub.x, us5 = ub.y, us6 = ub.z, us7 = ub.w;
        float4 na, nb4;
        float un;
        if (i == 0) { na = u4[2]; nb4 = u4[3]; un = na.x; }
        else        { un = nbv; }
        const int t0 = base + 8 * i;

        // ---- geometry for 8 samples -> 12 packed n-values
        float nx[8], ny[8], nz[8], uu[9];
        uu[0]=us0; uu[1]=us1; uu[2]=us2; uu[3]=us3; uu[4]=us4; uu[5]=us5; uu[6]=us6; uu[7]=us7; uu[8]=un;
        float ts7;
        #pragma unroll
        for (int s = 0; s < 8; ++s) {
            const float ts = fmaf(scaleT, (float)(t0 + s) + uu[s], tn);
            if (s == 7) ts7 = ts;
            const float x = fmaf(dx, ts, ox), y = fmaf(dy, ts, oy), z = fmaf(dz, ts, oz);
            nx[s] = fmaf(x - mn0, g0, -1.0f);
            ny[s] = fmaf(y - mn1, g1, -1.0f);
            nz[s] = fmaf(z - mn2, g2, -1.0f);
        }
        bool ib[8];
        float dl[8];
        #pragma unroll
        for (int s = 0; s < 8; ++s) {
            ib[s] = (fabsf(nx[s]) <= 1.f) & (fabsf(ny[s]) <= 1.f) & (fabsf(nz[s]) <= 1.f);
            dl[s] = dscale * (1.0f + uu[s + 1] - uu[s]);
        }
        if (t0 + 7 == N_SAMPLES - 1) dl[7] = (tf + 1.0f - ts7) * dnorm;

        // packs: A=(s0,s1) B=(s2,s3) C=(s4,s5) D=(s6,s7)
        const ull p0A = pk2(nx[0], nx[1]), p1A = pk2(ny[0], ny[1]), p2A = pk2(nz[0], nz[1]);
        const ull p0B = pk2(nx[2], nx[3]), p1B = pk2(ny[2], ny[3]), p2B = pk2(nz[2], nz[3]);
        const ull p0C = pk2(nx[4], nx[5]), p1C = pk2(ny[4], ny[5]), p2C = pk2(nz[4], nz[5]);
        const ull p0D = pk2(nx[6], nx[7]), p1D = pk2(ny[6], ny[7]), p2D = pk2(nz[6], nz[7]);

        ull prA = 0, pgA = 0, pbA = 0, pdA = 0;
        ull prB = 0, pgB = 0, pbB = 0, pdB = 0;
        ull prC = 0, pgC = 0, pbC = 0, pdC = 0;
        ull prD = 0, pgD = 0, pbD = 0, pdD = 0;

        #pragma unroll 2
        for (int j = 0; j < HID; ++j) {
            const ulonglong2 wab = sAB[j];
            const ulonglong2 wcd = sCD[j];
            ull hA = fma2_(p0A, wab.x, fma2_(p1A, wab.y, fma2_(p2A, wcd.x, wcd.y)));
            ull hB = fma2_(p0B, wab.x, fma2_(p1B, wab.y, fma2_(p2B, wcd.x, wcd.y)));
            ull hC = fma2_(p0C, wab.x, fma2_(p1C, wab.y, fma2_(p2C, wcd.x, wcd.y)));
            ull hD = fma2_(p0D, wab.x, fma2_(p1D, wab.y, fma2_(p2D, wcd.x, wcd.y)));
            hA = relu2(hA); hB = relu2(hB); hC = relu2(hC); hD = relu2(hD);
            const ulonglong2 wef = sEF[j];
            const ulonglong2 wgh = sGH[j];
            prA = fma2_(hA, wef.x, prA); pgA = fma2_(hA, wef.y, pgA);
            pbA = fma2_(hA, wgh.x, pbA); pdA = fma2_(hA, wgh.y, pdA);
            prB = fma2_(hB, wef.x, prB); pgB = fma2_(hB, wef.y, pgB);
            pbB = fma2_(hB, wgh.x, pbB); pdB = fma2_(hB, wgh.y, pdB);
            prC = fma2_(hC, wef.x, prC); pgC = fma2_(hC, wef.y, pgC);
            pbC = fma2_(hC, wgh.x, pbC); pdC = fma2_(hC, wgh.y, pdC);
            prD = fma2_(hD, wef.x, prD); pgD = fma2_(hD, wef.y, pgD);
            pbD = fma2_(hD, wgh.x, pbD); pdD = fma2_(hD, wgh.y, pdD);
        }

        // ---- unpack + sequential compositing (order matters)
        float cr0, cr1, cg0, cg1, cb0, cb1, dd0, dd1;
        #pragma unroll
        for (int q = 0; q < 4; ++q) {
            ull pr, pg, pb, pd;
            if (q == 0)      { pr = prA; pg = pgA; pb = pbA; pd = pdA; }
            else if (q == 1) { pr = prB; pg = pgB; pb = pbB; pd = pdB; }
            else if (q == 2) { pr = prC; pg = pgC; pb = pbC; pd = pdC; }
            else             { pr = prD; pg = pgD; pb = pbD; pd = pdD; }
            upk2(pr, cr0, cr1); upk2(pg, cg0, cg1); upk2(pb, cb0, cb1); upk2(pd, dd0, dd1);
            const int s0 = 2 * q, s1 = 2 * q + 1;
            {
                const float cr = sigmoidf_fast(cr0 + bcr), cg = sigmoidf_fast(cg0 + bcg), cb = sigmoidf_fast(cb0 + bcb);
                float den = softplusf_fast(dd0 + bdd); if (!ib[s0]) den = 0.0f;
                const float sd = den * dl[s0], esd = __expf(-sd);
                const float wl = e_run - e_run * esd;
                ar = fmaf(wl, cr, ar); ag = fmaf(wl, cg, ag); ab = fmaf(wl, cb, ab); aw += wl;
                e_run *= esd; Psum += sd;
            }
            {
                const float cr = sigmoidf_fast(cr1 + bcr), cg = sigmoidf_fast(cg1 + bcg), cb = sigmoidf_fast(cb1 + bcb);
                float den = softplusf_fast(dd1 + bdd); if (!ib[s1]) den = 0.0f;
                const float sd = den * dl[s1], esd = __expf(-sd);
                const float wl = e_run - e_run * esd;
                ar = fmaf(wl, cr, ar); ag = fmaf(wl, cg, ag); ab = fmaf(wl, cb, ab); aw += wl;
                e_run *= esd; Psum += sd;
            }
        }

        ua = na; ub = nb4;
    }

    // ---- warp exclusive scan of optical depth -> per-lane transmittance base
    float inc = Psum;
    #pragma unroll
    for (int off = 1; off < 32; off <<= 1) {
        float y = __shfl_up_sync(FULL, inc, off);
        if (lane >= off) inc += y;
    }
    float excl = __shfl_up_sync(FULL, inc, 1);
    if (lane == 0) excl = 0.0f;
    const float sc = __expf(-excl);
    ar *= sc; ag *= sc; ab *= sc; aw *= sc;

    #pragma unroll
    for (int off = 16; off > 0; off >>= 1) {
        ar += __shfl_xor_sync(FULL, ar, off);
        ag += __shfl_xor_sync(FULL, ag, off);
        ab += __shfl_xor_sync(FULL, ab, off);
        aw += __shfl_xor_sync(FULL, aw, off);
    }

    if (lane == 0)
        reinterpret_cast<float4*>(out)[r] = make_float4(ar, ag, ab, aw);
}

extern "C" void kernel_launch(void* const* d_in, const int* in_sizes, int n_in,
                              void* d_out, int out_size) {
    const float* o    = (const float*)d_in[0];
    const float* dI   = (const float*)d_in[1];
    const float* aabb = (const float*)d_in[2];
    const float* u    = (const float*)d_in[3];
    const float* W1   = (const float*)d_in[4];
    const float* b1   = (const float*)d_in[5];
    const float* Wc   = (const float*)d_in[6];
    const float* bc   = (const float*)d_in[7];
    const float* Wd   = (const float*)d_in[8];
    const float* bd   = (const float*)d_in[9];
    float* out = (float*)d_out;

    dim3 grid(N_RAYS / WARPS_PER_BLOCK);
    dim3 block(WARPS_PER_BLOCK * 32);
    nerf_render_kernel<<<grid, block>>>(o, dI, aabb, u, W1, b1, Wc, bc, Wd, bd, out);
}

// round 9
// speedup vs baseline: 1.4231x; 1.2418x over previous
#include <cuda_runtime.h>
#include <cstdint>

#define FULL 0xFFFFFFFFu

constexpr int N_RAYS    = 8192;
constexpr int N_SAMPLES = 512;
constexpr int HID       = 32;
constexpr int WARPS_PER_BLOCK = 8;
constexpr int TPT       = 16;   // samples per thread

using ull = unsigned long long;

// ---- packed f32x2 helpers (sm_103a) ----
__device__ __forceinline__ ull pk2(float lo, float hi) {
    ull r; asm("mov.b64 %0, {%1, %2};" : "=l"(r) : "f"(lo), "f"(hi)); return r;
}
__device__ __forceinline__ void upk2(ull v, float& lo, float& hi) {
    asm("mov.b64 {%0, %1}, %2;" : "=f"(lo), "=f"(hi) : "l"(v));
}
__device__ __forceinline__ ull fma2_(ull a, ull b, ull c) {
    ull r; asm("fma.rn.f32x2 %0, %1, %2, %3;" : "=l"(r) : "l"(a), "l"(b), "l"(c)); return r;
}
// relu per half via FMNMX (alu pipe); pair aliasing -> no real movs
__device__ __forceinline__ ull relu2(ull h) {
    float lo, hi; upk2(h, lo, hi);
    lo = fmaxf(lo, 0.0f); hi = fmaxf(hi, 0.0f);
    return pk2(lo, hi);
}

__device__ __forceinline__ float sigmoidf_fast(float x) {
    return __fdividef(1.0f, 1.0f + __expf(-x));
}
__device__ __forceinline__ float softplusf_fast(float x) {
    return fmaxf(x, 0.0f) + __logf(1.0f + __expf(-fabsf(x)));
}

__global__ __launch_bounds__(WARPS_PER_BLOCK * 32, 2)
void nerf_render_kernel(
    const float* __restrict__ o,    // [N,3]
    const float* __restrict__ dI,   // [N,3]
    const float* __restrict__ aabb, // [2,3]
    const float* __restrict__ u,    // [N,512]
    const float* __restrict__ W1,   // [3,32]
    const float* __restrict__ b1,   // [32]
    const float* __restrict__ Wc,   // [32,3]
    const float* __restrict__ bc,   // [3]
    const float* __restrict__ Wd,   // [32,1]
    const float* __restrict__ bd,   // [1]
    float* __restrict__ out)        // [N,4]
{
    // layer-2 weight tables (block-wide): one LDS.128 each per j
    __shared__ ulonglong2 sEF[HID], sGH[HID];
    // per-ray fused layer-1: sRayAB[w][j] = { (A_j,A_j), (B_j,B_j) }
    __shared__ ulonglong2 sRayAB[WARPS_PER_BLOCK][HID];
    __shared__ float sbias[4];

    const int tx = threadIdx.x;
    if (tx < HID) {
        const float cx = Wc[3 * tx], cy = Wc[3 * tx + 1];
        const float cz = Wc[3 * tx + 2], cw = Wd[tx];
        sEF[tx] = make_ulonglong2(pk2(cx, cx), pk2(cy, cy));
        sGH[tx] = make_ulonglong2(pk2(cz, cz), pk2(cw, cw));
    }
    if (tx == HID) { sbias[0] = bc[0]; sbias[1] = bc[1]; sbias[2] = bc[2]; sbias[3] = bd[0]; }
    __syncthreads();

    const int warp = tx >> 5;
    const int lane = tx & 31;
    const int r = blockIdx.x * WARPS_PER_BLOCK + warp;

    const float ox = o[3 * r], oy = o[3 * r + 1], oz = o[3 * r + 2];
    const float dx = dI[3 * r], dy = dI[3 * r + 1], dz = dI[3 * r + 2];
    const float mn0 = aabb[0], mn1 = aabb[1], mn2 = aabb[2];
    const float mx0 = aabb[3], mx1 = aabb[4], mx2 = aabb[5];

    float t1, t2;
    t1 = (mn0 - ox) / dx; t2 = (mx0 - ox) / dx;
    float tn = fminf(t1, t2), tf = fmaxf(t1, t2);
    t1 = (mn1 - oy) / dy; t2 = (mx1 - oy) / dy;
    tn = fmaxf(tn, fminf(t1, t2)); tf = fminf(tf, fmaxf(t1, t2));
    t1 = (mn2 - oz) / dz; t2 = (mx2 - oz) / dz;
    tn = fmaxf(tn, fminf(t1, t2)); tf = fminf(tf, fmaxf(t1, t2));
    tn = fmaxf(tn, 0.0f);

    if (!(tn < tf)) {
        if (lane == 0) reinterpret_cast<float4*>(out)[r] = make_float4(0.f, 0.f, 0.f, 0.f);
        return;
    }

    const float dnorm  = sqrtf(dx * dx + dy * dy + dz * dz);
    const float scaleT = (tf - tn) * (1.0f / (float)N_SAMPLES);
    const float dscale = scaleT * dnorm;
    const float g0 = 2.0f / (mx0 - mn0);
    const float g1 = 2.0f / (mx1 - mn1);
    const float g2 = 2.0f / (mx2 - mn2);
    const float bcr = sbias[0], bcg = sbias[1], bcb = sbias[2], bdd = sbias[3];

    // ---- affine ndc:  ndc_k(ts) = Q_k * ts + P_k
    const float Q0 = dx * g0, Q1 = dy * g1, Q2 = dz * g2;
    const float P0 = fmaf(ox - mn0, g0, -1.0f);
    const float P1 = fmaf(oy - mn1, g1, -1.0f);
    const float P2 = fmaf(oz - mn2, g2, -1.0f);

    // ---- fused layer-1: lane j computes (A_j, B_j); h_j(ts) = relu(A_j ts + B_j)
    {
        const float wx = W1[lane], wy = W1[HID + lane], wz = W1[2 * HID + lane], wb = b1[lane];
        const float A = fmaf(wx, Q0, fmaf(wy, Q1, wz * Q2));
        const float B = fmaf(wx, P0, fmaf(wy, P1, fmaf(wz, P2, wb)));
        sRayAB[warp][lane] = make_ulonglong2(pk2(A, A), pk2(B, B));
    }
    __syncwarp();

    const float4* u4 = reinterpret_cast<const float4*>(u + (size_t)r * N_SAMPLES) + lane * 4;
    float4 ua = u4[0], ub = u4[1];
    const float nbv = __shfl_down_sync(FULL, ua.x, 1);   // lane 31's value unused (t==511 path)

    const int base = lane * TPT;

    float e_run = 1.0f, Psum = 0.0f;
    float ar = 0.f, ag = 0.f, ab = 0.f, aw = 0.f;

    #pragma unroll 1
    for (int i = 0; i < 2; ++i) {
        float uu[9];
        uu[0]=ua.x; uu[1]=ua.y; uu[2]=ua.z; uu[3]=ua.w;
        uu[4]=ub.x; uu[5]=ub.y; uu[6]=ub.z; uu[7]=ub.w;
        float4 na, nb4;
        if (i == 0) { na = u4[2]; nb4 = u4[3]; uu[8] = na.x; }
        else        { uu[8] = nbv; }
        const int t0 = base + 8 * i;

        // ---- ts + inbox for 8 samples
        float tsv[8];
        bool ib[8];
        #pragma unroll
        for (int s = 0; s < 8; ++s) {
            const float ts = fmaf(scaleT, (float)(t0 + s) + uu[s], tn);
            tsv[s] = ts;
            const float n0 = fmaf(Q0, ts, P0);
            const float n1 = fmaf(Q1, ts, P1);
            const float n2 = fmaf(Q2, ts, P2);
            ib[s] = (fabsf(n0) <= 1.f) & (fabsf(n1) <= 1.f) & (fabsf(n2) <= 1.f);
        }
        float dl[8];
        #pragma unroll
        for (int s = 0; s < 8; ++s)
            dl[s] = dscale * (1.0f + uu[s + 1] - uu[s]);
        if (t0 + 7 == N_SAMPLES - 1) dl[7] = (tf + 1.0f - tsv[7]) * dnorm;

        // ts packs: A=(s0,s1) B=(s2,s3) C=(s4,s5) D=(s6,s7)
        const ull ptsA = pk2(tsv[0], tsv[1]);
        const ull ptsB = pk2(tsv[2], tsv[3]);
        const ull ptsC = pk2(tsv[4], tsv[5]);
        const ull ptsD = pk2(tsv[6], tsv[7]);

        ull prA = 0, pgA = 0, pbA = 0, pdA = 0;
        ull prB = 0, pgB = 0, pbB = 0, pdB = 0;
        ull prC = 0, pgC = 0, pbC = 0, pdC = 0;
        ull prD = 0, pgD = 0, pbD = 0, pdD = 0;

        #pragma unroll 4
        for (int j = 0; j < HID; ++j) {
            const ulonglong2 wab = sRayAB[warp][j];     // (A,A),(B,B)
            ull hA = fma2_(ptsA, wab.x, wab.y);
            ull hB = fma2_(ptsB, wab.x, wab.y);
            ull hC = fma2_(ptsC, wab.x, wab.y);
            ull hD = fma2_(ptsD, wab.x, wab.y);
            hA = relu2(hA); hB = relu2(hB); hC = relu2(hC); hD = relu2(hD);
            const ulonglong2 wef = sEF[j];
            const ulonglong2 wgh = sGH[j];
            prA = fma2_(hA, wef.x, prA); pgA = fma2_(hA, wef.y, pgA);
            pbA = fma2_(hA, wgh.x, pbA); pdA = fma2_(hA, wgh.y, pdA);
            prB = fma2_(hB, wef.x, prB); pgB = fma2_(hB, wef.y, pgB);
            pbB = fma2_(hB, wgh.x, pbB); pdB = fma2_(hB, wgh.y, pdB);
            prC = fma2_(hC, wef.x, prC); pgC = fma2_(hC, wef.y, pgC);
            pbC = fma2_(hC, wgh.x, pbC); pdC = fma2_(hC, wgh.y, pdC);
            prD = fma2_(hD, wef.x, prD); pgD = fma2_(hD, wef.y, pgD);
            pbD = fma2_(hD, wgh.x, pbD); pdD = fma2_(hD, wgh.y, pdD);
        }

        // ---- unpack + sequential compositing (order matters)
        float cr0, cr1, cg0, cg1, cb0, cb1, dd0, dd1;
        #pragma unroll
        for (int q = 0; q < 4; ++q) {
            ull pr, pg, pb, pd;
            if (q == 0)      { pr = prA; pg = pgA; pb = pbA; pd = pdA; }
            else if (q == 1) { pr = prB; pg = pgB; pb = pbB; pd = pdB; }
            else if (q == 2) { pr = prC; pg = pgC; pb = pbC; pd = pdC; }
            else             { pr = prD; pg = pgD; pb = pbD; pd = pdD; }
            upk2(pr, cr0, cr1); upk2(pg, cg0, cg1); upk2(pb, cb0, cb1); upk2(pd, dd0, dd1);
            const int s0 = 2 * q, s1 = 2 * q + 1;
            {
                const float cr = sigmoidf_fast(cr0 + bcr), cg = sigmoidf_fast(cg0 + bcg), cb = sigmoidf_fast(cb0 + bcb);
                float den = softplusf_fast(dd0 + bdd); if (!ib[s0]) den = 0.0f;
                const float sd = den * dl[s0], esd = __expf(-sd);
                const float wl = e_run - e_run * esd;
                ar = fmaf(wl, cr, ar); ag = fmaf(wl, cg, ag); ab = fmaf(wl, cb, ab); aw += wl;
                e_run *= esd; Psum += sd;
            }
            {
                const float cr = sigmoidf_fast(cr1 + bcr), cg = sigmoidf_fast(cg1 + bcg), cb = sigmoidf_fast(cb1 + bcb);
                float den = softplusf_fast(dd1 + bdd); if (!ib[s1]) den = 0.0f;
                const float sd = den * dl[s1], esd = __expf(-sd);
                const float wl = e_run - e_run * esd;
                ar = fmaf(wl, cr, ar); ag = fmaf(wl, cg, ag); ab = fmaf(wl, cb, ab); aw += wl;
                e_run *= esd; Psum += sd;
            }
        }

        ua = na; ub = nb4;
    }

    // ---- warp exclusive scan of optical depth -> per-lane transmittance base
    float inc = Psum;
    #pragma unroll
    for (int off = 1; off < 32; off <<= 1) {
        float y = __shfl_up_sync(FULL, inc, off);
        if (lane >= off) inc += y;
    }
    float excl = __shfl_up_sync(FULL, inc, 1);
    if (lane == 0) excl = 0.0f;
    const float sc = __expf(-excl);
    ar *= sc; ag *= sc; ab *= sc; aw *= sc;

    #pragma unroll
    for (int off = 16; off > 0; off >>= 1) {
        ar += __shfl_xor_sync(FULL, ar, off);
        ag += __shfl_xor_sync(FULL, ag, off);
        ab += __shfl_xor_sync(FULL, ab, off);
        aw += __shfl_xor_sync(FULL, aw, off);
    }

    if (lane == 0)
        reinterpret_cast<float4*>(out)[r] = make_float4(ar, ag, ab, aw);
}

extern "C" void kernel_launch(void* const* d_in, const int* in_sizes, int n_in,
                              void* d_out, int out_size) {
    const float* o    = (const float*)d_in[0];
    const float* dI   = (const float*)d_in[1];
    const float* aabb = (const float*)d_in[2];
    const float* u    = (const float*)d_in[3];
    const float* W1   = (const float*)d_in[4];
    const float* b1   = (const float*)d_in[5];
    const float* Wc   = (const float*)d_in[6];
    const float* bc   = (const float*)d_in[7];
    const float* Wd   = (const float*)d_in[8];
    const float* bd   = (const float*)d_in[9];
    float* out = (float*)d_out;

    dim3 grid(N_RAYS / WARPS_PER_BLOCK);
    dim3 block(WARPS_PER_BLOCK * 32);
    nerf_render_kernel<<<grid, block>>>(o, dI, aabb, u, W1, b1, Wc, bc, Wd, bd, out);
}

// round 10
// speedup vs baseline: 2.1164x; 1.4872x over previous
#include <cuda_runtime.h>
#include <cstdint>

#define FULL 0xFFFFFFFFu

constexpr int N_RAYS    = 8192;
constexpr int N_SAMPLES = 512;
constexpr int HID       = 32;
constexpr int WPB       = 8;    // warps per block
constexpr int TPT       = 16;   // samples per thread

__device__ __forceinline__ float sigmoidf_fast(float x) {
    return __fdividef(1.0f, 1.0f + __expf(-x));
}
__device__ __forceinline__ float softplusf_fast(float x) {
    return fmaxf(x, 0.0f) + __logf(1.0f + __expf(-fabsf(x)));
}

__global__ __launch_bounds__(WPB * 32)
void nerf_render_kernel(
    const float* __restrict__ o,    // [N,3]
    const float* __restrict__ dI,   // [N,3]
    const float* __restrict__ aabb, // [2,3]
    const float* __restrict__ u,    // [N,512]
    const float* __restrict__ W1,   // [3,32]
    const float* __restrict__ b1,   // [32]
    const float* __restrict__ Wc,   // [32,3]
    const float* __restrict__ bc,   // [3]
    const float* __restrict__ Wd,   // [32,1]
    const float* __restrict__ bd,   // [1]
    float* __restrict__ out)        // [N,4]
{
    const float INF = __int_as_float(0x7f800000);

    __shared__ float4 sABT[WPB][HID];     // per-warp: (A_j, B_j, t*_j, 0)
    __shared__ float4 sC[HID];            // block: (Wc0, Wc1, Wc2, Wd)
    __shared__ float  sBPt[WPB][HID + 1]; // per-warp sorted breakpoint times (+INF pad)
    __shared__ int    sBPj[WPB][HID];     // payload: unit index
    __shared__ float  sbias[4];

    const int tx = threadIdx.x;
    if (tx < HID)
        sC[tx] = make_float4(Wc[3 * tx], Wc[3 * tx + 1], Wc[3 * tx + 2], Wd[tx]);
    if (tx == HID) { sbias[0] = bc[0]; sbias[1] = bc[1]; sbias[2] = bc[2]; sbias[3] = bd[0]; }
    __syncthreads();

    const int warp = tx >> 5;
    const int lane = tx & 31;
    const int r = blockIdx.x * WPB + warp;

    const float ox = o[3 * r], oy = o[3 * r + 1], oz = o[3 * r + 2];
    const float dx = dI[3 * r], dy = dI[3 * r + 1], dz = dI[3 * r + 2];
    const float mn0 = aabb[0], mn1 = aabb[1], mn2 = aabb[2];
    const float mx0 = aabb[3], mx1 = aabb[4], mx2 = aabb[5];

    float t1, t2;
    t1 = (mn0 - ox) / dx; t2 = (mx0 - ox) / dx;
    float tn = fminf(t1, t2), tf = fmaxf(t1, t2);
    t1 = (mn1 - oy) / dy; t2 = (mx1 - oy) / dy;
    tn = fmaxf(tn, fminf(t1, t2)); tf = fminf(tf, fmaxf(t1, t2));
    t1 = (mn2 - oz) / dz; t2 = (mx2 - oz) / dz;
    tn = fmaxf(tn, fminf(t1, t2)); tf = fminf(tf, fmaxf(t1, t2));
    tn = fmaxf(tn, 0.0f);

    if (!(tn < tf)) {   // inactive ray (warp-uniform)
        if (lane == 0) reinterpret_cast<float4*>(out)[r] = make_float4(0.f, 0.f, 0.f, 0.f);
        return;
    }

    const float dnorm  = sqrtf(dx * dx + dy * dy + dz * dz);
    const float scaleT = (tf - tn) * (1.0f / (float)N_SAMPLES);
    const float dscale = scaleT * dnorm;
    const float g0 = 2.0f / (mx0 - mn0);
    const float g1 = 2.0f / (mx1 - mn1);
    const float g2 = 2.0f / (mx2 - mn2);
    const float bcr = sbias[0], bcg = sbias[1], bcb = sbias[2], bdd = sbias[3];

    // affine ndc:  ndc_k(ts) = Q_k * ts + P_k
    const float Q0 = dx * g0, Q1 = dy * g1, Q2 = dz * g2;
    const float P0 = fmaf(ox - mn0, g0, -1.0f);
    const float P1 = fmaf(oy - mn1, g1, -1.0f);
    const float P2 = fmaf(oz - mn2, g2, -1.0f);

    // ---- per-unit affine coefficients + breakpoint (lane = unit j)
    {
        const float wx = W1[lane], wy = W1[HID + lane], wz = W1[2 * HID + lane], wb = b1[lane];
        const float A = fmaf(wx, Q0, fmaf(wy, Q1, wz * Q2));
        const float B = fmaf(wx, P0, fmaf(wy, P1, fmaf(wz, P2, wb)));
        float tstar = (A == 0.0f) ? INF : __fdividef(-B, A);
        if (tstar != tstar) tstar = INF;   // NaN safety
        sABT[warp][lane] = make_float4(A, B, tstar, 0.0f);

        // ---- bitonic sort of (t*, j) across the warp
        float key = tstar; int val = lane;
        #pragma unroll
        for (int size = 2; size <= 32; size <<= 1) {
            #pragma unroll
            for (int stride = size >> 1; stride > 0; stride >>= 1) {
                const float pk = __shfl_xor_sync(FULL, key, stride);
                const int   pv = __shfl_xor_sync(FULL, val, stride);
                const bool ascending = ((lane & size) == 0);
                const bool lower = ((lane & stride) == 0);
                const bool takeMin = (ascending == lower);
                const bool doSwap = takeMin ? (pk < key) : (pk > key);
                if (doSwap) { key = pk; val = pv; }
            }
        }
        sBPt[warp][lane] = key;
        sBPj[warp][lane] = val;
        if (lane == 0) sBPt[warp][HID] = INF;
    }
    __syncwarp();

    // ---- jitter values
    const float4* u4 = reinterpret_cast<const float4*>(u + (size_t)r * N_SAMPLES) + lane * 4;
    float4 ua = u4[0], ub = u4[1];
    const float nbv = __shfl_down_sync(FULL, ua.x, 1);   // lane 31 unused (t==511 path)

    const int base = lane * TPT;
    const float t1v = fmaf(scaleT, (float)base + ua.x, tn);  // this lane's first sample t

    // ---- initial active-set sums at t1v (crossing-rule semantics: active iff
    //      (t* <= t1v) ? (A > 0) : (A < 0 || (A == 0 && B > 0)) )
    float SA0 = 0.f, SA1 = 0.f, SA2 = 0.f, SA3 = 0.f;
    float SB0 = 0.f, SB1 = 0.f, SB2 = 0.f, SB3 = 0.f;
    #pragma unroll 4
    for (int j = 0; j < HID; ++j) {
        const float4 abt = sABT[warp][j];
        const float4 c   = sC[j];
        bool act;
        if (abt.z <= t1v) act = (abt.x > 0.0f);
        else              act = (abt.x < 0.0f) || ((abt.x == 0.0f) && (abt.y > 0.0f));
        const float aa = act ? abt.x : 0.0f;
        const float bb = act ? abt.y : 0.0f;
        SA0 = fmaf(aa, c.x, SA0); SA1 = fmaf(aa, c.y, SA1);
        SA2 = fmaf(aa, c.z, SA2); SA3 = fmaf(aa, c.w, SA3);
        SB0 = fmaf(bb, c.x, SB0); SB1 = fmaf(bb, c.y, SB1);
        SB2 = fmaf(bb, c.z, SB2); SB3 = fmaf(bb, c.w, SB3);
    }

    // ---- breakpoint cursor = count of sorted t* <= t1v (same comparison!)
    int kp = 0;
    {
        const float* bt = sBPt[warp];
        if (bt[31] <= t1v) kp = 32;
        else {
            if (bt[kp + 15] <= t1v) kp += 16;
            if (bt[kp + 7]  <= t1v) kp += 8;
            if (bt[kp + 3]  <= t1v) kp += 4;
            if (bt[kp + 1]  <= t1v) kp += 2;
            if (bt[kp]      <= t1v) kp += 1;
        }
    }
    float nbp = sBPt[warp][kp];

    float e_run = 1.0f, Psum = 0.0f;
    float ar = 0.f, ag = 0.f, ab = 0.f, aw = 0.f;

    #pragma unroll 1
    for (int i = 0; i < 2; ++i) {
        float uu[9];
        uu[0] = ua.x; uu[1] = ua.y; uu[2] = ua.z; uu[3] = ua.w;
        uu[4] = ub.x; uu[5] = ub.y; uu[6] = ub.z; uu[7] = ub.w;
        float4 na, nb4;
        if (i == 0) { na = u4[2]; nb4 = u4[3]; uu[8] = na.x; }
        else        { uu[8] = nbv; }
        const int t0 = base + 8 * i;

        #pragma unroll
        for (int s = 0; s < 8; ++s) {
            const float ts = fmaf(scaleT, (float)(t0 + s) + uu[s], tn);

            // apply breakpoint crossings (rare)
            while (nbp <= ts) {
                const int jj = sBPj[warp][kp];
                const float4 abt = sABT[warp][jj];
                const float4 c   = sC[jj];
                const float sgn = (abt.x > 0.0f) ? 1.0f : -1.0f;
                const float sa = sgn * abt.x, sb = sgn * abt.y;
                SA0 = fmaf(sa, c.x, SA0); SA1 = fmaf(sa, c.y, SA1);
                SA2 = fmaf(sa, c.z, SA2); SA3 = fmaf(sa, c.w, SA3);
                SB0 = fmaf(sb, c.x, SB0); SB1 = fmaf(sb, c.y, SB1);
                SB2 = fmaf(sb, c.z, SB2); SB3 = fmaf(sb, c.w, SB3);
                ++kp;
                nbp = sBPt[warp][kp];
            }

            // inbox test (same arithmetic as R8)
            const float n0 = fmaf(Q0, ts, P0);
            const float n1 = fmaf(Q1, ts, P1);
            const float n2 = fmaf(Q2, ts, P2);
            const bool ib = (fabsf(n0) <= 1.f) & (fabsf(n1) <= 1.f) & (fabsf(n2) <= 1.f);

            float dlv = dscale * (1.0f + uu[s + 1] - uu[s]);
            if (t0 + s == N_SAMPLES - 1) dlv = (tf + 1.0f - ts) * dnorm;

            // piecewise-linear logits
            const float lr  = fmaf(SA0, ts, SB0);
            const float lg  = fmaf(SA1, ts, SB1);
            const float lb  = fmaf(SA2, ts, SB2);
            const float ldd = fmaf(SA3, ts, SB3);

            // epilogue (identical numerics to R8)
            const float cr = sigmoidf_fast(lr + bcr);
            const float cg = sigmoidf_fast(lg + bcg);
            const float cb = sigmoidf_fast(lb + bcb);
            float den = softplusf_fast(ldd + bdd);
            if (!ib) den = 0.0f;
            const float sd  = den * dlv;
            const float esd = __expf(-sd);
            const float wl  = e_run - e_run * esd;
            ar = fmaf(wl, cr, ar); ag = fmaf(wl, cg, ag); ab = fmaf(wl, cb, ab); aw += wl;
            e_run *= esd;
            Psum  += sd;
        }

        ua = na; ub = nb4;
    }

    // ---- warp exclusive scan of optical depth -> per-lane transmittance base
    float inc = Psum;
    #pragma unroll
    for (int off = 1; off < 32; off <<= 1) {
        float y = __shfl_up_sync(FULL, inc, off);
        if (lane >= off) inc += y;
    }
    float excl = __shfl_up_sync(FULL, inc, 1);
    if (lane == 0) excl = 0.0f;
    const float sc = __expf(-excl);
    ar *= sc; ag *= sc; ab *= sc; aw *= sc;

    #pragma unroll
    for (int off = 16; off > 0; off >>= 1) {
        ar += __shfl_xor_sync(FULL, ar, off);
        ag += __shfl_xor_sync(FULL, ag, off);
        ab += __shfl_xor_sync(FULL, ab, off);
        aw += __shfl_xor_sync(FULL, aw, off);
    }

    if (lane == 0)
        reinterpret_cast<float4*>(out)[r] = make_float4(ar, ag, ab, aw);
}

extern "C" void kernel_launch(void* const* d_in, const int* in_sizes, int n_in,
                              void* d_out, int out_size) {
    const float* o    = (const float*)d_in[0];
    const float* dI   = (const float*)d_in[1];
    const float* aabb = (const float*)d_in[2];
    const float* u    = (const float*)d_in[3];
    const float* W1   = (const float*)d_in[4];
    const float* b1   = (const float*)d_in[5];
    const float* Wc   = (const float*)d_in[6];
    const float* bc   = (const float*)d_in[7];
    const float* Wd   = (const float*)d_in[8];
    const float* bd   = (const float*)d_in[9];
    float* out = (float*)d_out;

    dim3 grid(N_RAYS / WPB);
    dim3 block(WPB * 32);
    nerf_render_kernel<<<grid, block>>>(o, dI, aabb, u, W1, b1, Wc, bc, Wd, bd, out);
}

// round 11
// speedup vs baseline: 2.6195x; 1.2377x over previous
#include <cuda_runtime.h>
#include <cstdint>

#define FULL 0xFFFFFFFFu

constexpr int N_RAYS    = 8192;
constexpr int N_SAMPLES = 512;
constexpr int HID       = 32;
constexpr int WPB       = 8;    // warps per block
constexpr int TPT       = 16;   // samples per thread

__device__ __forceinline__ float sigmoidf_fast(float x) {
    return __fdividef(1.0f, 1.0f + __expf(-x));
}
__device__ __forceinline__ float softplusf_fast(float x) {
    return fmaxf(x, 0.0f) + __logf(1.0f + __expf(-fabsf(x)));
}

__global__ __launch_bounds__(WPB * 32, 4)
void nerf_render_kernel(
    const float* __restrict__ o,    // [N,3]
    const float* __restrict__ dI,   // [N,3]
    const float* __restrict__ aabb, // [2,3]
    const float* __restrict__ u,    // [N,512]
    const float* __restrict__ W1,   // [3,32]
    const float* __restrict__ b1,   // [32]
    const float* __restrict__ Wc,   // [32,3]
    const float* __restrict__ bc,   // [3]
    const float* __restrict__ Wd,   // [32,1]
    const float* __restrict__ bd,   // [1]
    float* __restrict__ out)        // [N,4]
{
    const float INF = __int_as_float(0x7f800000);

    __shared__ float4 sABT[WPB][HID];     // per-warp: (A_j, B_j, t*_j, 0)
    __shared__ float4 sC[HID];            // block: (Wc0, Wc1, Wc2, Wd)
    __shared__ float  sBPt[WPB][HID + 1]; // per-warp sorted breakpoint times (+INF pad)
    __shared__ int    sBPj[WPB][HID];     // payload: unit index
    __shared__ float  sbias[4];

    const int tx = threadIdx.x;
    if (tx < HID)
        sC[tx] = make_float4(Wc[3 * tx], Wc[3 * tx + 1], Wc[3 * tx + 2], Wd[tx]);
    if (tx == HID) { sbias[0] = bc[0]; sbias[1] = bc[1]; sbias[2] = bc[2]; sbias[3] = bd[0]; }
    __syncthreads();

    const int warp = tx >> 5;
    const int lane = tx & 31;
    const int r = blockIdx.x * WPB + warp;

    const float ox = o[3 * r], oy = o[3 * r + 1], oz = o[3 * r + 2];
    const float dx = dI[3 * r], dy = dI[3 * r + 1], dz = dI[3 * r + 2];
    const float mn0 = aabb[0], mn1 = aabb[1], mn2 = aabb[2];
    const float mx0 = aabb[3], mx1 = aabb[4], mx2 = aabb[5];

    float t1, t2;
    t1 = (mn0 - ox) / dx; t2 = (mx0 - ox) / dx;
    float tn = fminf(t1, t2), tf = fmaxf(t1, t2);
    t1 = (mn1 - oy) / dy; t2 = (mx1 - oy) / dy;
    tn = fmaxf(tn, fminf(t1, t2)); tf = fminf(tf, fmaxf(t1, t2));
    t1 = (mn2 - oz) / dz; t2 = (mx2 - oz) / dz;
    tn = fmaxf(tn, fminf(t1, t2)); tf = fminf(tf, fmaxf(t1, t2));
    tn = fmaxf(tn, 0.0f);

    if (!(tn < tf)) {   // inactive ray (warp-uniform)
        if (lane == 0) reinterpret_cast<float4*>(out)[r] = make_float4(0.f, 0.f, 0.f, 0.f);
        return;
    }

    const float dnorm  = sqrtf(dx * dx + dy * dy + dz * dz);
    const float scaleT = (tf - tn) * (1.0f / (float)N_SAMPLES);
    const float dscale = scaleT * dnorm;
    const float g0 = 2.0f / (mx0 - mn0);
    const float g1 = 2.0f / (mx1 - mn1);
    const float g2 = 2.0f / (mx2 - mn2);
    const float bcr = sbias[0], bcg = sbias[1], bcb = sbias[2], bdd = sbias[3];

    // affine ndc:  ndc_k(ts) = Q_k * ts + P_k
    const float Q0 = dx * g0, Q1 = dy * g1, Q2 = dz * g2;
    const float P0 = fmaf(ox - mn0, g0, -1.0f);
    const float P1 = fmaf(oy - mn1, g1, -1.0f);
    const float P2 = fmaf(oz - mn2, g2, -1.0f);

    // ---- Phase A: per-unit affine coeffs + breakpoint; base sums (activity at t=-inf)
    float bA0, bA1, bA2, bA3, bB0, bB1, bB2, bB3;
    float key; int val;
    {
        const float wx = W1[lane], wy = W1[HID + lane], wz = W1[2 * HID + lane], wb = b1[lane];
        const float A = fmaf(wx, Q0, fmaf(wy, Q1, wz * Q2));
        const float B = fmaf(wx, P0, fmaf(wy, P1, fmaf(wz, P2, wb)));
        float tstar = (A == 0.0f) ? INF : __fdividef(-B, A);
        if (tstar != tstar) tstar = INF;   // NaN safety
        sABT[warp][lane] = make_float4(A, B, tstar, 0.0f);

        const float4 c = sC[lane];
        const bool act0 = (A < 0.0f) || ((A == 0.0f) && (B > 0.0f));
        const float aa = act0 ? A : 0.0f;
        const float bb = act0 ? B : 0.0f;
        bA0 = aa * c.x; bA1 = aa * c.y; bA2 = aa * c.z; bA3 = aa * c.w;
        bB0 = bb * c.x; bB1 = bb * c.y; bB2 = bb * c.z; bB3 = bb * c.w;
        #pragma unroll
        for (int off = 16; off > 0; off >>= 1) {
            bA0 += __shfl_xor_sync(FULL, bA0, off);
            bA1 += __shfl_xor_sync(FULL, bA1, off);
            bA2 += __shfl_xor_sync(FULL, bA2, off);
            bA3 += __shfl_xor_sync(FULL, bA3, off);
            bB0 += __shfl_xor_sync(FULL, bB0, off);
            bB1 += __shfl_xor_sync(FULL, bB1, off);
            bB2 += __shfl_xor_sync(FULL, bB2, off);
            bB3 += __shfl_xor_sync(FULL, bB3, off);
        }

        // ---- Phase B: bitonic sort of (t*, j) across the warp
        key = tstar; val = lane;
        #pragma unroll
        for (int size = 2; size <= 32; size <<= 1) {
            #pragma unroll
            for (int stride = size >> 1; stride > 0; stride >>= 1) {
                const float pk = __shfl_xor_sync(FULL, key, stride);
                const int   pv = __shfl_xor_sync(FULL, val, stride);
                const bool ascending = ((lane & size) == 0);
                const bool lower = ((lane & stride) == 0);
                const bool takeMin = (ascending == lower);
                const bool doSwap = takeMin ? (pk < key) : (pk > key);
                if (doSwap) { key = pk; val = pv; }
            }
        }
        sBPt[warp][lane] = key;
        sBPj[warp][lane] = val;
        if (lane == 0) sBPt[warp][HID] = INF;
    }
    __syncwarp();

    // ---- Phase C: inclusive prefix-scan of crossing deltas in sorted order
    float dA0, dA1, dA2, dA3, dB0, dB1, dB2, dB3;
    {
        const float4 abtS = sABT[warp][val];
        const float4 cS   = sC[val];
        const float sg = (abtS.x > 0.0f) ? 1.0f : -1.0f;
        const float sa = sg * abtS.x, sb = sg * abtS.y;
        dA0 = sa * cS.x; dA1 = sa * cS.y; dA2 = sa * cS.z; dA3 = sa * cS.w;
        dB0 = sb * cS.x; dB1 = sb * cS.y; dB2 = sb * cS.z; dB3 = sb * cS.w;
        #pragma unroll
        for (int off = 1; off < 32; off <<= 1) {
            float t;
            t = __shfl_up_sync(FULL, dA0, off); if (lane >= off) dA0 += t;
            t = __shfl_up_sync(FULL, dA1, off); if (lane >= off) dA1 += t;
            t = __shfl_up_sync(FULL, dA2, off); if (lane >= off) dA2 += t;
            t = __shfl_up_sync(FULL, dA3, off); if (lane >= off) dA3 += t;
            t = __shfl_up_sync(FULL, dB0, off); if (lane >= off) dB0 += t;
            t = __shfl_up_sync(FULL, dB1, off); if (lane >= off) dB1 += t;
            t = __shfl_up_sync(FULL, dB2, off); if (lane >= off) dB2 += t;
            t = __shfl_up_sync(FULL, dB3, off); if (lane >= off) dB3 += t;
        }
    }

    // ---- jitter values
    const float4* u4 = reinterpret_cast<const float4*>(u + (size_t)r * N_SAMPLES) + lane * 4;
    float4 ua = u4[0], ub = u4[1];
    const float nbv = __shfl_down_sync(FULL, ua.x, 1);   // lane 31 unused (t==511 path)

    const int base = lane * TPT;
    const float t1v = fmaf(scaleT, (float)base + ua.x, tn);  // this lane's first sample t

    // ---- Phase D: breakpoint cursor = count of sorted t* <= t1v (same comparison!)
    int kp = 0;
    {
        const float* bt = sBPt[warp];
        if (bt[31] <= t1v) kp = 32;
        else {
            if (bt[kp + 15] <= t1v) kp += 16;
            if (bt[kp + 7]  <= t1v) kp += 8;
            if (bt[kp + 3]  <= t1v) kp += 4;
            if (bt[kp + 1]  <= t1v) kp += 2;
            if (bt[kp]      <= t1v) kp += 1;
        }
    }
    float nbp = sBPt[warp][kp];

    // initial sums = base + prefix[kp-1]
    float SA0, SA1, SA2, SA3, SB0, SB1, SB2, SB3;
    {
        const int src = (kp > 0) ? (kp - 1) : 0;
        float pA0 = __shfl_sync(FULL, dA0, src);
        float pA1 = __shfl_sync(FULL, dA1, src);
        float pA2 = __shfl_sync(FULL, dA2, src);
        float pA3 = __shfl_sync(FULL, dA3, src);
        float pB0 = __shfl_sync(FULL, dB0, src);
        float pB1 = __shfl_sync(FULL, dB1, src);
        float pB2 = __shfl_sync(FULL, dB2, src);
        float pB3 = __shfl_sync(FULL, dB3, src);
        if (kp == 0) { pA0 = pA1 = pA2 = pA3 = pB0 = pB1 = pB2 = pB3 = 0.0f; }
        SA0 = bA0 + pA0; SA1 = bA1 + pA1; SA2 = bA2 + pA2; SA3 = bA3 + pA3;
        SB0 = bB0 + pB0; SB1 = bB1 + pB1; SB2 = bB2 + pB2; SB3 = bB3 + pB3;
    }

    float e_run = 1.0f, Psum = 0.0f;
    float ar = 0.f, ag = 0.f, ab = 0.f, aw = 0.f;

    #pragma unroll 1
    for (int i = 0; i < 2; ++i) {
        float uu[9];
        uu[0] = ua.x; uu[1] = ua.y; uu[2] = ua.z; uu[3] = ua.w;
        uu[4] = ub.x; uu[5] = ub.y; uu[6] = ub.z; uu[7] = ub.w;
        float4 na, nb4;
        if (i == 0) { na = u4[2]; nb4 = u4[3]; uu[8] = na.x; }
        else        { uu[8] = nbv; }
        const int t0 = base + 8 * i;

        #pragma unroll
        for (int s = 0; s < 8; ++s) {
            const float ts = fmaf(scaleT, (float)(t0 + s) + uu[s], tn);

            // apply breakpoint crossings (rare)
            while (nbp <= ts) {
                const int jj = sBPj[warp][kp];
                const float4 abt = sABT[warp][jj];
                const float4 c   = sC[jj];
                const float sgn = (abt.x > 0.0f) ? 1.0f : -1.0f;
                const float sa = sgn * abt.x, sb = sgn * abt.y;
                SA0 = fmaf(sa, c.x, SA0); SA1 = fmaf(sa, c.y, SA1);
                SA2 = fmaf(sa, c.z, SA2); SA3 = fmaf(sa, c.w, SA3);
                SB0 = fmaf(sb, c.x, SB0); SB1 = fmaf(sb, c.y, SB1);
                SB2 = fmaf(sb, c.z, SB2); SB3 = fmaf(sb, c.w, SB3);
                ++kp;
                nbp = sBPt[warp][kp];
            }

            // inbox test
            const float n0 = fmaf(Q0, ts, P0);
            const float n1 = fmaf(Q1, ts, P1);
            const float n2 = fmaf(Q2, ts, P2);
            const bool ib = (fabsf(n0) <= 1.f) & (fabsf(n1) <= 1.f) & (fabsf(n2) <= 1.f);

            float dlv = dscale * (1.0f + uu[s + 1] - uu[s]);
            if (t0 + s == N_SAMPLES - 1) dlv = (tf + 1.0f - ts) * dnorm;

            // piecewise-linear logits
            const float lr  = fmaf(SA0, ts, SB0);
            const float lg  = fmaf(SA1, ts, SB1);
            const float lb  = fmaf(SA2, ts, SB2);
            const float ldd = fmaf(SA3, ts, SB3);

            // epilogue
            const float cr = sigmoidf_fast(lr + bcr);
            const float cg = sigmoidf_fast(lg + bcg);
            const float cb = sigmoidf_fast(lb + bcb);
            float den = softplusf_fast(ldd + bdd);
            if (!ib) den = 0.0f;
            const float sd  = den * dlv;
            const float esd = __expf(-sd);
            const float wl  = e_run - e_run * esd;
            ar = fmaf(wl, cr, ar); ag = fmaf(wl, cg, ag); ab = fmaf(wl, cb, ab); aw += wl;
            e_run *= esd;
            Psum  += sd;
        }

        ua = na; ub = nb4;
    }

    // ---- warp exclusive scan of optical depth -> per-lane transmittance base
    float inc = Psum;
    #pragma unroll
    for (int off = 1; off < 32; off <<= 1) {
        float y = __shfl_up_sync(FULL, inc, off);
        if (lane >= off) inc += y;
    }
    float excl = __shfl_up_sync(FULL, inc, 1);
    if (lane == 0) excl = 0.0f;
    const float sc = __expf(-excl);
    ar *= sc; ag *= sc; ab *= sc; aw *= sc;

    #pragma unroll
    for (int off = 16; off > 0; off >>= 1) {
        ar += __shfl_xor_sync(FULL, ar, off);
        ag += __shfl_xor_sync(FULL, ag, off);
        ab += __shfl_xor_sync(FULL, ab, off);
        aw += __shfl_xor_sync(FULL, aw, off);
    }

    if (lane == 0)
        reinterpret_cast<float4*>(out)[r] = make_float4(ar, ag, ab, aw);
}

extern "C" void kernel_launch(void* const* d_in, const int* in_sizes, int n_in,
                              void* d_out, int out_size) {
    const float* o    = (const float*)d_in[0];
    const float* dI   = (const float*)d_in[1];
    const float* aabb = (const float*)d_in[2];
    const float* u    = (const float*)d_in[3];
    const float* W1   = (const float*)d_in[4];
    const float* b1   = (const float*)d_in[5];
    const float* Wc   = (const float*)d_in[6];
    const float* bc   = (const float*)d_in[7];
    const float* Wd   = (const float*)d_in[8];
    const float* bd   = (const float*)d_in[9];
    float* out = (float*)d_out;

    dim3 grid(N_RAYS / WPB);
    dim3 block(WPB * 32);
    nerf_render_kernel<<<grid, block>>>(o, dI, aabb, u, W1, b1, Wc, bc, Wd, bd, out);
}

// round 12
// speedup vs baseline: 2.8501x; 1.0880x over previous
#include <cuda_runtime.h>
#include <cstdint>

#define FULL 0xFFFFFFFFu

constexpr int N_RAYS    = 8192;
constexpr int N_SAMPLES = 512;
constexpr int HID       = 32;
constexpr int WPB       = 8;    // warps per block
constexpr int TPT       = 16;   // samples per thread

__device__ __forceinline__ float sigmoidf_fast(float x) {
    return __fdividef(1.0f, 1.0f + __expf(-x));
}
__device__ __forceinline__ float softplusf_fast(float x) {
    return fmaxf(x, 0.0f) + __logf(1.0f + __expf(-fabsf(x)));
}

__global__ __launch_bounds__(WPB * 32, 4)
void nerf_render_kernel(
    const float* __restrict__ o,    // [N,3]
    const float* __restrict__ dI,   // [N,3]
    const float* __restrict__ aabb, // [2,3]
    const float* __restrict__ u,    // [N,512]
    const float* __restrict__ W1,   // [3,32]
    const float* __restrict__ b1,   // [32]
    const float* __restrict__ Wc,   // [32,3]
    const float* __restrict__ bc,   // [3]
    const float* __restrict__ Wd,   // [32,1]
    const float* __restrict__ bd,   // [1]
    float* __restrict__ out)        // [N,4]
{
    const float INF = __int_as_float(0x7f800000);

    __shared__ float4 sABT[WPB][HID];     // per-warp: (A_j, B_j, t*_j, 0)
    __shared__ float4 sC[HID];            // block: (Wc0, Wc1, Wc2, Wd)
    __shared__ float  sBPt[WPB][HID + 1]; // per-warp sorted breakpoint times (+INF pad)
    __shared__ int    sBPj[WPB][HID];     // payload: unit index
    __shared__ float  sbias[4];

    const int tx = threadIdx.x;
    if (tx < HID)
        sC[tx] = make_float4(Wc[3 * tx], Wc[3 * tx + 1], Wc[3 * tx + 2], Wd[tx]);
    if (tx == HID) { sbias[0] = bc[0]; sbias[1] = bc[1]; sbias[2] = bc[2]; sbias[3] = bd[0]; }
    __syncthreads();

    const int warp = tx >> 5;
    const int lane = tx & 31;
    const int r = blockIdx.x * WPB + warp;

    const float ox = o[3 * r], oy = o[3 * r + 1], oz = o[3 * r + 2];
    const float dx = dI[3 * r], dy = dI[3 * r + 1], dz = dI[3 * r + 2];
    const float mn0 = aabb[0], mn1 = aabb[1], mn2 = aabb[2];
    const float mx0 = aabb[3], mx1 = aabb[4], mx2 = aabb[5];

    float t1, t2;
    t1 = (mn0 - ox) / dx; t2 = (mx0 - ox) / dx;
    float tn = fminf(t1, t2), tf = fmaxf(t1, t2);
    t1 = (mn1 - oy) / dy; t2 = (mx1 - oy) / dy;
    tn = fmaxf(tn, fminf(t1, t2)); tf = fminf(tf, fmaxf(t1, t2));
    t1 = (mn2 - oz) / dz; t2 = (mx2 - oz) / dz;
    tn = fmaxf(tn, fminf(t1, t2)); tf = fminf(tf, fmaxf(t1, t2));
    const float tn_raw = tn;      // unclamped slab entry: inbox(t) <=> tn_raw <= t <= tf
    tn = fmaxf(tn, 0.0f);

    if (!(tn < tf)) {   // inactive ray (warp-uniform)
        if (lane == 0) reinterpret_cast<float4*>(out)[r] = make_float4(0.f, 0.f, 0.f, 0.f);
        return;
    }

    const float dnorm  = sqrtf(dx * dx + dy * dy + dz * dz);
    const float scaleT = (tf - tn) * (1.0f / (float)N_SAMPLES);
    const float dscale = scaleT * dnorm;
    const float g0 = 2.0f / (mx0 - mn0);
    const float g1 = 2.0f / (mx1 - mn1);
    const float g2 = 2.0f / (mx2 - mn2);
    const float bcr = sbias[0], bcg = sbias[1], bcb = sbias[2], bdd = sbias[3];

    // affine ndc:  ndc_k(ts) = Q_k * ts + P_k  (used only in the prologue now)
    const float Q0 = dx * g0, Q1 = dy * g1, Q2 = dz * g2;
    const float P0 = fmaf(ox - mn0, g0, -1.0f);
    const float P1 = fmaf(oy - mn1, g1, -1.0f);
    const float P2 = fmaf(oz - mn2, g2, -1.0f);

    // ---- Phase A: per-unit affine coeffs + breakpoint; base sums (activity at t=-inf)
    float bA0, bA1, bA2, bA3, bB0, bB1, bB2, bB3;
    float key; int val;
    {
        const float wx = W1[lane], wy = W1[HID + lane], wz = W1[2 * HID + lane], wb = b1[lane];
        const float A = fmaf(wx, Q0, fmaf(wy, Q1, wz * Q2));
        const float B = fmaf(wx, P0, fmaf(wy, P1, fmaf(wz, P2, wb)));
        float tstar = (A == 0.0f) ? INF : __fdividef(-B, A);
        if (tstar != tstar) tstar = INF;   // NaN safety
        sABT[warp][lane] = make_float4(A, B, tstar, 0.0f);

        const float4 c = sC[lane];
        const bool act0 = (A < 0.0f) || ((A == 0.0f) && (B > 0.0f));
        const float aa = act0 ? A : 0.0f;
        const float bb = act0 ? B : 0.0f;
        bA0 = aa * c.x; bA1 = aa * c.y; bA2 = aa * c.z; bA3 = aa * c.w;
        bB0 = bb * c.x; bB1 = bb * c.y; bB2 = bb * c.z; bB3 = bb * c.w;
        #pragma unroll
        for (int off = 16; off > 0; off >>= 1) {
            bA0 += __shfl_xor_sync(FULL, bA0, off);
            bA1 += __shfl_xor_sync(FULL, bA1, off);
            bA2 += __shfl_xor_sync(FULL, bA2, off);
            bA3 += __shfl_xor_sync(FULL, bA3, off);
            bB0 += __shfl_xor_sync(FULL, bB0, off);
            bB1 += __shfl_xor_sync(FULL, bB1, off);
            bB2 += __shfl_xor_sync(FULL, bB2, off);
            bB3 += __shfl_xor_sync(FULL, bB3, off);
        }

        // ---- Phase B: bitonic sort of (t*, j) across the warp
        key = tstar; val = lane;
        #pragma unroll
        for (int size = 2; size <= 32; size <<= 1) {
            #pragma unroll
            for (int stride = size >> 1; stride > 0; stride >>= 1) {
                const float pk = __shfl_xor_sync(FULL, key, stride);
                const int   pv = __shfl_xor_sync(FULL, val, stride);
                const bool ascending = ((lane & size) == 0);
                const bool lower = ((lane & stride) == 0);
                const bool takeMin = (ascending == lower);
                const bool doSwap = takeMin ? (pk < key) : (pk > key);
                if (doSwap) { key = pk; val = pv; }
            }
        }
        sBPt[warp][lane] = key;
        sBPj[warp][lane] = val;
        if (lane == 0) sBPt[warp][HID] = INF;
    }
    __syncwarp();

    // ---- Phase C: inclusive prefix-scan of crossing deltas in sorted order
    float dA0, dA1, dA2, dA3, dB0, dB1, dB2, dB3;
    {
        const float4 abtS = sABT[warp][val];
        const float4 cS   = sC[val];
        const float sg = (abtS.x > 0.0f) ? 1.0f : -1.0f;
        const float sa = sg * abtS.x, sb = sg * abtS.y;
        dA0 = sa * cS.x; dA1 = sa * cS.y; dA2 = sa * cS.z; dA3 = sa * cS.w;
        dB0 = sb * cS.x; dB1 = sb * cS.y; dB2 = sb * cS.z; dB3 = sb * cS.w;
        #pragma unroll
        for (int off = 1; off < 32; off <<= 1) {
            float t;
            t = __shfl_up_sync(FULL, dA0, off); if (lane >= off) dA0 += t;
            t = __shfl_up_sync(FULL, dA1, off); if (lane >= off) dA1 += t;
            t = __shfl_up_sync(FULL, dA2, off); if (lane >= off) dA2 += t;
            t = __shfl_up_sync(FULL, dA3, off); if (lane >= off) dA3 += t;
            t = __shfl_up_sync(FULL, dB0, off); if (lane >= off) dB0 += t;
            t = __shfl_up_sync(FULL, dB1, off); if (lane >= off) dB1 += t;
            t = __shfl_up_sync(FULL, dB2, off); if (lane >= off) dB2 += t;
            t = __shfl_up_sync(FULL, dB3, off); if (lane >= off) dB3 += t;
        }
    }

    // ---- jitter values
    const float4* u4 = reinterpret_cast<const float4*>(u + (size_t)r * N_SAMPLES) + lane * 4;
    float4 ua = u4[0], ub = u4[1];
    const float nbv = __shfl_down_sync(FULL, ua.x, 1);   // lane 31 unused (t==511 path)

    const int base = lane * TPT;
    const float t1v = fmaf(scaleT, (float)base + ua.x, tn);  // this lane's first sample t

    // ---- Phase D: breakpoint cursor = count of sorted t* <= t1v (same comparison!)
    int kp = 0;
    {
        const float* bt = sBPt[warp];
        if (bt[31] <= t1v) kp = 32;
        else {
            if (bt[kp + 15] <= t1v) kp += 16;
            if (bt[kp + 7]  <= t1v) kp += 8;
            if (bt[kp + 3]  <= t1v) kp += 4;
            if (bt[kp + 1]  <= t1v) kp += 2;
            if (bt[kp]      <= t1v) kp += 1;
        }
    }
    float nbp = sBPt[warp][kp];

    // initial sums = base + prefix[kp-1]  (+ output biases folded into SB)
    float SA0, SA1, SA2, SA3, SB0, SB1, SB2, SB3;
    {
        const int src = (kp > 0) ? (kp - 1) : 0;
        float pA0 = __shfl_sync(FULL, dA0, src);
        float pA1 = __shfl_sync(FULL, dA1, src);
        float pA2 = __shfl_sync(FULL, dA2, src);
        float pA3 = __shfl_sync(FULL, dA3, src);
        float pB0 = __shfl_sync(FULL, dB0, src);
        float pB1 = __shfl_sync(FULL, dB1, src);
        float pB2 = __shfl_sync(FULL, dB2, src);
        float pB3 = __shfl_sync(FULL, dB3, src);
        if (kp == 0) { pA0 = pA1 = pA2 = pA3 = pB0 = pB1 = pB2 = pB3 = 0.0f; }
        SA0 = bA0 + pA0; SA1 = bA1 + pA1; SA2 = bA2 + pA2; SA3 = bA3 + pA3;
        SB0 = (bB0 + pB0) + bcr; SB1 = (bB1 + pB1) + bcg;
        SB2 = (bB2 + pB2) + bcb; SB3 = (bB3 + pB3) + bdd;
    }

    float e_run = 1.0f, Psum = 0.0f;
    float ar = 0.f, ag = 0.f, ab = 0.f, aw = 0.f;

    #pragma unroll 1
    for (int i = 0; i < 2; ++i) {
        float uu[9];
        uu[0] = ua.x; uu[1] = ua.y; uu[2] = ua.z; uu[3] = ua.w;
        uu[4] = ub.x; uu[5] = ub.y; uu[6] = ub.z; uu[7] = ub.w;
        float4 na, nb4;
        if (i == 0) { na = u4[2]; nb4 = u4[3]; uu[8] = na.x; }
        else        { uu[8] = nbv; }
        const int t0 = base + 8 * i;

        #pragma unroll
        for (int s = 0; s < 8; ++s) {
            const float ts = fmaf(scaleT, (float)(t0 + s) + uu[s], tn);

            // apply breakpoint crossings (rare)
            while (nbp <= ts) {
                const int jj = sBPj[warp][kp];
                const float4 abt = sABT[warp][jj];
                const float4 c   = sC[jj];
                const float sgn = (abt.x > 0.0f) ? 1.0f : -1.0f;
                const float sa = sgn * abt.x, sb = sgn * abt.y;
                SA0 = fmaf(sa, c.x, SA0); SA1 = fmaf(sa, c.y, SA1);
                SA2 = fmaf(sa, c.z, SA2); SA3 = fmaf(sa, c.w, SA3);
                SB0 = fmaf(sb, c.x, SB0); SB1 = fmaf(sb, c.y, SB1);
                SB2 = fmaf(sb, c.z, SB2); SB3 = fmaf(sb, c.w, SB3);
                ++kp;
                nbp = sBPt[warp][kp];
            }

            // inbox <=> ts within the (unclamped) slab interval
            const bool ib = (ts >= tn_raw) & (ts <= tf);

            float dlv = dscale * (1.0f + uu[s + 1] - uu[s]);
            if (t0 + s == N_SAMPLES - 1) dlv = (tf + 1.0f - ts) * dnorm;

            // piecewise-linear logits (biases pre-folded into SB)
            const float lr  = fmaf(SA0, ts, SB0);
            const float lg  = fmaf(SA1, ts, SB1);
            const float lb  = fmaf(SA2, ts, SB2);
            const float ldd = fmaf(SA3, ts, SB3);

            // epilogue
            const float cr = sigmoidf_fast(lr);
            const float cg = sigmoidf_fast(lg);
            const float cb = sigmoidf_fast(lb);
            float den = softplusf_fast(ldd);
            if (!ib) den = 0.0f;
            const float sd  = den * dlv;
            const float esd = __expf(-sd);
            const float wl  = fmaf(-e_run, esd, e_run);   // e_run*(1-esd)
            ar = fmaf(wl, cr, ar); ag = fmaf(wl, cg, ag); ab = fmaf(wl, cb, ab); aw += wl;
            e_run *= esd;
            Psum  += sd;
        }

        ua = na; ub = nb4;
    }

    // ---- warp exclusive scan of optical depth -> per-lane transmittance base
    float inc = Psum;
    #pragma unroll
    for (int off = 1; off < 32; off <<= 1) {
        float y = __shfl_up_sync(FULL, inc, off);
        if (lane >= off) inc += y;
    }
    float excl = __shfl_up_sync(FULL, inc, 1);
    if (lane == 0) excl = 0.0f;
    const float sc = __expf(-excl);
    ar *= sc; ag *= sc; ab *= sc; aw *= sc;

    #pragma unroll
    for (int off = 16; off > 0; off >>= 1) {
        ar += __shfl_xor_sync(FULL, ar, off);
        ag += __shfl_xor_sync(FULL, ag, off);
        ab += __shfl_xor_sync(FULL, ab, off);
        aw += __shfl_xor_sync(FULL, aw, off);
    }

    if (lane == 0)
        reinterpret_cast<float4*>(out)[r] = make_float4(ar, ag, ab, aw);
}

extern "C" void kernel_launch(void* const* d_in, const int* in_sizes, int n_in,
                              void* d_out, int out_size) {
    const float* o    = (const float*)d_in[0];
    const float* dI   = (const float*)d_in[1];
    const float* aabb = (const float*)d_in[2];
    const float* u    = (const float*)d_in[3];
    const float* W1   = (const float*)d_in[4];
    const float* b1   = (const float*)d_in[5];
    const float* Wc   = (const float*)d_in[6];
    const float* bc   = (const float*)d_in[7];
    const float* Wd   = (const float*)d_in[8];
    const float* bd   = (const float*)d_in[9];
    float* out = (float*)d_out;

    dim3 grid(N_RAYS / WPB);
    dim3 block(WPB * 32);
    nerf_render_kernel<<<grid, block>>>(o, dI, aabb, u, W1, b1, Wc, bc, Wd, bd, out);
}